// round 11
// baseline (speedup 1.0000x reference)
#include <cuda_runtime.h>
#include <math_constants.h>

// DarkChannel fused, column-walking with register carry (no vertical reread):
// Each block walks TILES_PER_SEG consecutive 15-row y-tiles of a 256-col strip.
// The 15 raw channel-min rows needed by the next tile's van Herk suffix array
// are captured in registers while streaming the current tile's prefix rows, so
// steady state loads each input row exactly once (1.0x vertical redundancy).
//   phase 1 (per tile): suffix mins of carried rows + stream 15 new rows -> smem
//   phase 2 (per tile): horizontal 15-min from smem (float4 LDS) -> out
//
// img [16,3,1024,1024] f32 -> out [16,1,1024,1024] f32, +inf border erosion.

#define IMG_H 1024
#define IMG_W 1024
#define IMG_B 16
#define CH_STRIDE (IMG_H * IMG_W)
#define YTILE 15
#define NUM_TY 69
#define XSPAN 256
#define HALO 8
#define SROW (XSPAN + 2 * HALO)          // 272
#define NTHREADS 288                     // 272 active in phase 1
#define TILES_PER_SEG 6
#define NSEG 12                          // ceil(69 / 6)

__device__ __forceinline__ float cmin1_raw(const float* r) {
    float c0 = __ldg(r);
    float c1 = __ldg(r + CH_STRIDE);
    float c2 = __ldg(r + 2 * CH_STRIDE);
    return fminf(fminf(c0, c1), c2);
}

template <bool CHECKY>
__device__ __forceinline__ float cmin1(const float* p, int y, bool vx) {
    if (!vx || (CHECKY && (unsigned)y >= (unsigned)IMG_H)) {
        return CUDART_INF_F;
    }
    return cmin1_raw(p + (size_t)y * IMG_W);
}

// Steady-state tile: n[] holds raw cmin rows y0-7 .. y0+7.
// Produces 15 eroded rows into smem, refills n[] with rows y0+8 .. y0+22.
template <bool CHECKY>
__device__ __forceinline__ void tile_p1(const float* p, bool vx, int y0,
                                        float* s, float (&n)[YTILE]) {
    // suffix mins in place (raw values no longer needed afterwards)
#pragma unroll
    for (int t = YTILE - 2; t >= 0; --t) {
        n[t] = fminf(n[t], n[t + 1]);
    }
    s[0] = n[0];

    float m[YTILE];                      // capture rows for next tile
    float g = CUDART_INF_F;
#pragma unroll
    for (int r = 1; r < YTILE; ++r) {
        float v = cmin1<CHECKY>(p, y0 + 7 + r, vx);   // rows y0+8 .. y0+21
        m[r - 1] = v;
        g = fminf(g, v);
        s[r * SROW] = fminf(n[r], g);
    }
    m[YTILE - 1] = cmin1<CHECKY>(p, y0 + 22, vx);     // row y0+22

#pragma unroll
    for (int t = 0; t < YTILE; ++t) n[t] = m[t];
}

// Phase 2: horizontal 15-min from smem, 4 outputs/iteration (proven R4 form).
__device__ __forceinline__ void tile_p2(const float* sV, float* outb,
                                        int y0, int X0, int tid) {
    const int vrows = min(YTILE, IMG_H - y0);
    const int nq = (XSPAN / 4) * vrows;               // 64 quads per row

    for (int i = tid; i < nq; i += NTHREADS) {
        const int r = i >> 6;
        const int c = i & 63;
        const float* row = &sV[r * SROW];
        const int L0 = (c << 2) + HALO;

        float f[20];
#pragma unroll
        for (int q = 0; q < 5; ++q) {
            float4 v = *reinterpret_cast<const float4*>(&row[L0 - 8 + 4 * q]);
            f[q * 4 + 0] = v.x;
            f[q * 4 + 1] = v.y;
            f[q * 4 + 2] = v.z;
            f[q * 4 + 3] = v.w;
        }

        float core = f[4];
#pragma unroll
        for (int k = 5; k <= 15; ++k) core = fminf(core, f[k]);

        float p23   = fminf(f[2], f[3]);
        float p1617 = fminf(f[16], f[17]);

        float4 o;
        o.x = fminf(core, fminf(f[1], p23));
        o.y = fminf(core, fminf(p23, f[16]));
        o.z = fminf(core, fminf(f[3], p1617));
        o.w = fminf(core, fminf(p1617, f[18]));

        float* op = outb + (size_t)(y0 + r) * IMG_W + X0 + (c << 2);
        *reinterpret_cast<float4*>(op) = o;
    }
}

extern "C" __global__ __launch_bounds__(NTHREADS, 3)
void k_fused(const float* __restrict__ img, float* __restrict__ out) {
    __shared__ float sV[YTILE * SROW];                // 16320 B

    const int tid = threadIdx.x;
    const int bx  = blockIdx.x;                       // x strip 0..3
    const int seg = blockIdx.y;                       // 0..11
    const int b   = blockIdx.z;
    const int X0  = bx * XSPAN;

    const int ty_begin = seg * TILES_PER_SEG;
    const int ty_end   = min(ty_begin + TILES_PER_SEG, NUM_TY);

    const bool active = tid < SROW;
    const int gx = X0 - HALO + tid;
    const bool vx = active && ((unsigned)gx < (unsigned)IMG_W);
    const float* p = img + (size_t)b * 3 * CH_STRIDE + gx;
    float* outb = out + (size_t)b * IMG_H * IMG_W;

    // prologue: fill n[] with raw rows (ty_begin*15 - 7) .. (+7)
    float n[YTILE];
    if (active) {
        const int y0 = ty_begin * YTILE;
        if (ty_begin == 0) {
#pragma unroll
            for (int t = 0; t < YTILE; ++t) n[t] = cmin1<true>(p, y0 - 7 + t, vx);
        } else {
#pragma unroll
            for (int t = 0; t < YTILE; ++t) n[t] = cmin1<false>(p, y0 - 7 + t, vx);
        }
    }

#pragma unroll 1
    for (int ty = ty_begin; ty < ty_end; ++ty) {
        const int y0 = ty * YTILE;

        if (active) {
            if (ty <= 66) {                           // rows up to y0+22 valid
                tile_p1<false>(p, vx, y0, &sV[tid], n);
            } else {
                tile_p1<true>(p, vx, y0, &sV[tid], n);
            }
        }
        __syncthreads();

        tile_p2(sV, outb, y0, X0, tid);
        __syncthreads();
    }
}

extern "C" void kernel_launch(void* const* d_in, const int* in_sizes, int n_in,
                              void* d_out, int out_size) {
    const float* img = (const float*)d_in[0];
    float* out = (float*)d_out;

    dim3 grid(IMG_W / XSPAN, NSEG, IMG_B);            // 4 x 12 x 16 = 768
    k_fused<<<grid, NTHREADS>>>(img, out);
}

// round 12
// speedup vs baseline: 1.1027x; 1.1027x over previous
#include <cuda_runtime.h>
#include <math_constants.h>

// DarkChannel fused (R4 champion skeleton + micro-opts):
//   phase 1: channel-min(C=3) + vertical 15-min van Herk (float2/thread) -> smem
//   phase 2: horizontal 15-min from smem (5x LDS.128 per 4 outputs),
//            streaming (__stcs) output stores, interior fast path.
//
// img [16,3,1024,1024] f32 -> out [16,1,1024,1024] f32, +inf border erosion.

#define IMG_H 1024
#define IMG_W 1024
#define IMG_B 16
#define CH_STRIDE (IMG_H * IMG_W)
#define YTILE 15
#define NUM_TY 69
#define XSPAN 512
#define HALO 8
#define SROW (XSPAN + 2 * HALO)          // 528
#define NTHREADS 288                     // 264 active in phase 1

__device__ __forceinline__ float2 min2(float2 a, float2 b) {
    return make_float2(fminf(a.x, b.x), fminf(a.y, b.y));
}

template <bool CHECKY>
__device__ __forceinline__ float2 cmin2(const float* p, int y, bool vx) {
    if (!vx || (CHECKY && (unsigned)y >= (unsigned)IMG_H)) {
        return make_float2(CUDART_INF_F, CUDART_INF_F);
    }
    const float* r = p + (size_t)y * IMG_W;
    float2 c0 = *reinterpret_cast<const float2*>(r);
    float2 c1 = *reinterpret_cast<const float2*>(r + CH_STRIDE);
    float2 c2 = *reinterpret_cast<const float2*>(r + 2 * CH_STRIDE);
    return min2(min2(c0, c1), c2);
}

// Vertical van Herk (window == block == 15) for one float2 column pair.
template <bool CHECKY>
__device__ __forceinline__ void vert(const float* p, bool vx, int y0, float* s) {
    float2 h[YTILE];
#pragma unroll
    for (int t = 0; t < YTILE; ++t) {
        h[t] = cmin2<CHECKY>(p, y0 - 7 + t, vx);        // rows y0-7 .. y0+7
    }
#pragma unroll
    for (int t = YTILE - 2; t >= 0; --t) {
        h[t] = min2(h[t], h[t + 1]);                    // suffix mins
    }

    *reinterpret_cast<float2*>(&s[0]) = h[0];

    float2 g = make_float2(CUDART_INF_F, CUDART_INF_F);
#pragma unroll
    for (int r = 1; r < YTILE; ++r) {
        g = min2(g, cmin2<CHECKY>(p, y0 + 7 + r, vx));  // next-block prefix
        *reinterpret_cast<float2*>(&s[r * SROW]) = min2(h[r], g);
    }
}

// One horizontal 15-min group: 4 outputs from 20 smem floats, streaming store.
__device__ __forceinline__ void hgroup(const float* row, int L0, float* op) {
    float f[20];
#pragma unroll
    for (int q = 0; q < 5; ++q) {
        float4 v = *reinterpret_cast<const float4*>(&row[L0 - 8 + 4 * q]);
        f[q * 4 + 0] = v.x;
        f[q * 4 + 1] = v.y;
        f[q * 4 + 2] = v.z;
        f[q * 4 + 3] = v.w;
    }

    float core = f[4];
#pragma unroll
    for (int k = 5; k <= 15; ++k) core = fminf(core, f[k]);

    float p23   = fminf(f[2], f[3]);
    float p1617 = fminf(f[16], f[17]);

    float4 o;
    o.x = fminf(core, fminf(f[1], p23));
    o.y = fminf(core, fminf(p23, f[16]));
    o.z = fminf(core, fminf(f[3], p1617));
    o.w = fminf(core, fminf(p1617, f[18]));

    __stcs(reinterpret_cast<float4*>(op), o);           // evict-first store
}

extern "C" __global__ __launch_bounds__(NTHREADS, 4)
void k_fused(const float* __restrict__ img, float* __restrict__ out) {
    __shared__ float sV[YTILE * SROW];                  // 31680 B

    const int tid = threadIdx.x;
    const int bx  = blockIdx.x;                         // x strip 0..1
    const int ty  = blockIdx.y;                         // y tile 0..68
    const int b   = blockIdx.z;
    const int y0  = ty * YTILE;
    const int X0  = bx * XSPAN;

    // ---- Phase 1: vertical erosion of SROW cols (incl. +/-8 halo) ----
    if (tid < SROW / 2) {                               // 264 active
        const int lc = tid << 1;
        const int gx = X0 - HALO + lc;
        const bool vx = (unsigned)gx < (unsigned)IMG_W;
        const float* p = img + (size_t)b * 3 * CH_STRIDE + gx;
        if (ty >= 1 && ty <= 66) {
            vert<false>(p, vx, y0, &sV[lc]);
        } else {
            vert<true>(p, vx, y0, &sV[lc]);
        }
    }

    __syncthreads();

    // ---- Phase 2: horizontal 15-min from smem ----
    float* outb = out + (size_t)b * IMG_H * IMG_W;

    if (ty != NUM_TY - 1) {
        // interior: all 15 rows valid; nq = 128*15 = 1920
#pragma unroll 1
        for (int i = tid; i < (XSPAN / 4) * YTILE; i += NTHREADS) {
            const int r = i >> 7;
            const int c = i & 127;
            hgroup(&sV[r * SROW], (c << 2) + HALO,
                   outb + (size_t)(y0 + r) * IMG_W + X0 + (c << 2));
        }
    } else {
        const int vrows = IMG_H - y0;                   // last tile: 4 rows
#pragma unroll 1
        for (int i = tid; i < (XSPAN / 4) * vrows; i += NTHREADS) {
            const int r = i >> 7;
            const int c = i & 127;
            hgroup(&sV[r * SROW], (c << 2) + HALO,
                   outb + (size_t)(y0 + r) * IMG_W + X0 + (c << 2));
        }
    }
}

extern "C" void kernel_launch(void* const* d_in, const int* in_sizes, int n_in,
                              void* d_out, int out_size) {
    const float* img = (const float*)d_in[0];
    float* out = (float*)d_out;

    dim3 grid(IMG_W / XSPAN, NUM_TY, IMG_B);            // 2 x 69 x 16
    k_fused<<<grid, NTHREADS>>>(img, out);
}